// round 3
// baseline (speedup 1.0000x reference)
#include <cuda_runtime.h>
#include <cuda_bf16.h>
#include <math.h>

// ---------------------------------------------------------------------------
// Problem constants
//   DIM=128, HALF=64, K=8, hd=512, out_dim = 23*64 = 1472, B = 32768
//   Pipeline:
//     FCNN1(lower=x[:, :64])  -> params1 [B,64,23]
//     RQS(upper=x[:,64:], params1) -> upper', ld1
//     FCNN2(upper')           -> params2 [B,64,23]
//     RQS(lower, params2)     -> lower', ld2
//     out = [concat(lower', upper') (B*128 floats)] ++ [logdet (B floats)]
// ---------------------------------------------------------------------------

#define MAXB 32768
#define HD   512
#define PDIM 1472

// Scratch (device globals: allocation-free per harness rules)
__device__ float g_h1[(size_t)MAXB * HD];
__device__ float g_h2[(size_t)MAXB * HD];
__device__ float g_params[(size_t)MAXB * PDIM];
__device__ float g_up[(size_t)MAXB * 64];
__device__ float g_ld[MAXB];

// ---------------------------------------------------------------------------
// SGEMM  C[M,N] = A[M,K] (row-major, row stride lda) * B[K,N] + bias, opt SiLU
// Tile: BM=128, BN=64, BK=8; 256 threads; per-thread 8x4 microtile.
// Requires: M%128==0, N%64==0, K%8==0 (true for all 6 calls).
// ---------------------------------------------------------------------------
template <int ACT>
__global__ __launch_bounds__(256)
void sgemm_bias(const float* __restrict__ A, int lda,
                const float* __restrict__ B,
                const float* __restrict__ bias,
                float* __restrict__ C,
                int M, int N, int K)
{
    constexpr int BM = 128, BN = 64, BK = 8, TM = 8, TN = 4;
    __shared__ float As[BK][BM];
    __shared__ float Bs[BK][BN];

    const int tid = threadIdx.x;
    const int tx  = tid & 15;   // N direction (16 * TN=4 -> 64)
    const int ty  = tid >> 4;   // M direction (16 * TM=8 -> 128)
    const int m0  = blockIdx.y * BM;
    const int n0  = blockIdx.x * BN;

    // A tile loaders: 128 rows x 8 k -> 4 floats / thread (float4 along K)
    const int arow = tid >> 1;
    const int akq  = (tid & 1) * 4;
    // B tile loaders: 8 rows x 64 cols -> 2 floats / thread (float2 along N)
    const int brow = tid >> 5;
    const int bcol = (tid & 31) * 2;

    float acc[TM][TN];
#pragma unroll
    for (int i = 0; i < TM; i++)
#pragma unroll
        for (int j = 0; j < TN; j++) acc[i][j] = 0.f;

    for (int k0 = 0; k0 < K; k0 += BK) {
        float4 av = *reinterpret_cast<const float4*>(
            A + (size_t)(m0 + arow) * lda + (k0 + akq));
        As[akq + 0][arow] = av.x;
        As[akq + 1][arow] = av.y;
        As[akq + 2][arow] = av.z;
        As[akq + 3][arow] = av.w;

        float2 bv = *reinterpret_cast<const float2*>(
            B + (size_t)(k0 + brow) * N + (n0 + bcol));
        Bs[brow][bcol]     = bv.x;
        Bs[brow][bcol + 1] = bv.y;

        __syncthreads();

#pragma unroll
        for (int kk = 0; kk < BK; kk++) {
            float4 a0 = *reinterpret_cast<const float4*>(&As[kk][ty * TM]);
            float4 a1 = *reinterpret_cast<const float4*>(&As[kk][ty * TM + 4]);
            float4 bb = *reinterpret_cast<const float4*>(&Bs[kk][tx * TN]);
            float aa[TM] = {a0.x, a0.y, a0.z, a0.w, a1.x, a1.y, a1.z, a1.w};
            float bv4[TN] = {bb.x, bb.y, bb.z, bb.w};
#pragma unroll
            for (int i = 0; i < TM; i++)
#pragma unroll
                for (int j = 0; j < TN; j++)
                    acc[i][j] = fmaf(aa[i], bv4[j], acc[i][j]);
        }
        __syncthreads();
    }

    // Epilogue
    float4 bsv = *reinterpret_cast<const float4*>(bias + n0 + tx * TN);
    const float bcols[TN] = {bsv.x, bsv.y, bsv.z, bsv.w};
#pragma unroll
    for (int i = 0; i < TM; i++) {
        const int m = m0 + ty * TM + i;
        float4 c;
        float v0 = acc[i][0] + bcols[0];
        float v1 = acc[i][1] + bcols[1];
        float v2 = acc[i][2] + bcols[2];
        float v3 = acc[i][3] + bcols[3];
        if (ACT) {  // SiLU
            v0 = v0 / (1.f + __expf(-v0));
            v1 = v1 / (1.f + __expf(-v1));
            v2 = v2 / (1.f + __expf(-v2));
            v3 = v3 / (1.f + __expf(-v3));
        }
        c.x = v0; c.y = v1; c.z = v2; c.w = v3;
        *reinterpret_cast<float4*>(C + (size_t)m * N + n0 + tx * TN) = c;
    }
}

// ---------------------------------------------------------------------------
// Rational-quadratic spline transform + log-det reduction.
// One block per sample (64 threads = 64 transformed dims).
// phase 0: transform upper half of x; write to g_up AND dout[:,64:]; ld->g_ld
// phase 1: transform lower half of x; write to dout[:, :64];
//          dout[B*128 + b] = g_ld[b] + sum(ld)
// ---------------------------------------------------------------------------
__device__ __forceinline__ float softplusf(float v)
{
    return (v > 20.f) ? v : log1pf(expf(v));
}

__global__ __launch_bounds__(64)
void rqs_kernel(const float* __restrict__ x,       // [B,128]
                const float* __restrict__ params,  // [B,64,23]
                float* __restrict__ y_scratch,     // g_up (phase 0) / unused
                float* __restrict__ dout,
                float* __restrict__ ld_buf,
                int phase, int Bn)
{
    const int b = blockIdx.x;
    const int j = threadIdx.x;  // 0..63

    const float xv = x[(size_t)b * 128 + (phase == 0 ? 64 + j : j)];
    const float* p = params + (size_t)b * PDIM + j * 23;

    float W[8], H[8], D7[7];
#pragma unroll
    for (int i = 0; i < 8; i++) W[i] = p[i];
#pragma unroll
    for (int i = 0; i < 8; i++) H[i] = p[8 + i];
#pragma unroll
    for (int i = 0; i < 7; i++) D7[i] = p[16 + i];

    // widths = MIN_W + (1 - 8*MIN_W) * softmax(W)
    float mw = W[0];
#pragma unroll
    for (int i = 1; i < 8; i++) mw = fmaxf(mw, W[i]);
    float sw = 0.f;
#pragma unroll
    for (int i = 0; i < 8; i++) { W[i] = expf(W[i] - mw); sw += W[i]; }
    const float invw = 1.f / sw;

    float mh = H[0];
#pragma unroll
    for (int i = 1; i < 8; i++) mh = fmaxf(mh, H[i]);
    float sh = 0.f;
#pragma unroll
    for (int i = 0; i < 8; i++) { H[i] = expf(H[i] - mh); sh += H[i]; }
    const float invh = 1.f / sh;

    float cumw[9], cumh[9];
    cumw[0] = 0.f; cumh[0] = 0.f;
#pragma unroll
    for (int i = 0; i < 8; i++) {
        cumw[i + 1] = cumw[i] + (0.001f + 0.992f * W[i] * invw);
        cumh[i + 1] = cumh[i] + (0.001f + 0.992f * H[i] * invh);
    }
#pragma unroll
    for (int i = 0; i < 9; i++) {
        cumw[i] = 2.f * cumw[i] - 1.f;
        cumh[i] = 2.f * cumh[i] - 1.f;
    }
    cumw[0] = -1.f; cumw[8] = 1.f;
    cumh[0] = -1.f; cumh[8] = 1.f;

    // derivs: d[0]=d[8]=MIN_D+softplus(const)=1 (compute as reference does)
    float d[9];
    const float CST = logf(expf(1.0f - 0.001f) - 1.0f);
    const float dpad = 0.001f + softplusf(CST);
    d[0] = dpad; d[8] = dpad;
#pragma unroll
    for (int i = 0; i < 7; i++) d[i + 1] = 0.001f + softplusf(D7[i]);

    // bin index: sum(x >= locs) - 1, locs[8] = cumw[8] + 1e-6
    int idx = 0;
#pragma unroll
    for (int i = 0; i < 9; i++) {
        float loc = cumw[i] + ((i == 8) ? 1e-6f : 0.f);
        idx += (xv >= loc) ? 1 : 0;
    }
    idx -= 1;
    idx = max(0, min(7, idx));

    float icw = 0.f, iw = 1.f, ich = 0.f, ih = 1.f, d0 = 1.f, d1 = 1.f;
#pragma unroll
    for (int i = 0; i < 8; i++) {
        if (i == idx) {
            icw = cumw[i]; iw = cumw[i + 1] - cumw[i];
            ich = cumh[i]; ih = cumh[i + 1] - cumh[i];
            d0 = d[i]; d1 = d[i + 1];
        }
    }
    const float idel = ih / iw;
    const float th   = (xv - icw) / iw;
    const float omt  = 1.f - th;
    const float t1mt = th * omt;

    const float numer = ih * (idel * th * th + d0 * t1mt);
    const float den   = idel + (d0 + d1 - 2.f * idel) * t1mt;
    float out = ich + numer / den;

    const float dnum = idel * idel *
        (d1 * th * th + 2.f * idel * t1mt + d0 * omt * omt);
    float lad = logf(dnum) - 2.f * logf(den);

    const bool inside = (xv >= -1.f) && (xv <= 1.f);
    if (!inside) { out = xv; lad = 0.f; }

    if (phase == 0) {
        y_scratch[(size_t)b * 64 + j] = out;
        dout[(size_t)b * 128 + 64 + j] = out;
    } else {
        dout[(size_t)b * 128 + j] = out;
    }

    // reduce lad over 64 lanes (2 warps)
    float v = lad;
#pragma unroll
    for (int off = 16; off > 0; off >>= 1)
        v += __shfl_down_sync(0xffffffffu, v, off);
    __shared__ float sred[2];
    if ((j & 31) == 0) sred[j >> 5] = v;
    __syncthreads();
    if (j == 0) {
        const float tot = sred[0] + sred[1];
        if (phase == 0) ld_buf[b] = tot;
        else dout[(size_t)Bn * 128 + b] = ld_buf[b] + tot;
    }
}

// ---------------------------------------------------------------------------
// Launch
// ---------------------------------------------------------------------------
extern "C" void kernel_launch(void* const* d_in, const int* in_sizes, int n_in,
                              void* d_out, int out_size)
{
    const float* x     = (const float*)d_in[0];
    const float* f1w1  = (const float*)d_in[1];
    const float* f1b1  = (const float*)d_in[2];
    const float* f1w2  = (const float*)d_in[3];
    const float* f1b2  = (const float*)d_in[4];
    const float* f1w3  = (const float*)d_in[5];
    const float* f1b3  = (const float*)d_in[6];
    const float* f2w1  = (const float*)d_in[7];
    const float* f2b1  = (const float*)d_in[8];
    const float* f2w2  = (const float*)d_in[9];
    const float* f2b2  = (const float*)d_in[10];
    const float* f2w3  = (const float*)d_in[11];
    const float* f2b3  = (const float*)d_in[12];
    float* out = (float*)d_out;

    const int B = in_sizes[0] / 128;

    float *h1, *h2, *pa, *up, *ld;
    cudaGetSymbolAddress((void**)&h1, g_h1);
    cudaGetSymbolAddress((void**)&h2, g_h2);
    cudaGetSymbolAddress((void**)&pa, g_params);
    cudaGetSymbolAddress((void**)&up, g_up);
    cudaGetSymbolAddress((void**)&ld, g_ld);

    const dim3 blk(256);
    const int MB = B / 128;  // M tiles

    // ---- FCNN1 on lower half of x ----
    sgemm_bias<1><<<dim3(HD / 64, MB), blk>>>(x, 128, f1w1, f1b1, h1, B, HD, 64);
    sgemm_bias<1><<<dim3(HD / 64, MB), blk>>>(h1, HD, f1w2, f1b2, h2, B, HD, HD);
    sgemm_bias<0><<<dim3(PDIM / 64, MB), blk>>>(h2, HD, f1w3, f1b3, pa, B, PDIM, HD);

    // ---- RQS on upper half ----
    rqs_kernel<<<B, 64>>>(x, pa, up, out, ld, 0, B);

    // ---- FCNN2 on transformed upper ----
    sgemm_bias<1><<<dim3(HD / 64, MB), blk>>>(up, 64, f2w1, f2b1, h1, B, HD, 64);
    sgemm_bias<1><<<dim3(HD / 64, MB), blk>>>(h1, HD, f2w2, f2b2, h2, B, HD, HD);
    sgemm_bias<0><<<dim3(PDIM / 64, MB), blk>>>(h2, HD, f2w3, f2b3, pa, B, PDIM, HD);

    // ---- RQS on lower half + final logdet ----
    rqs_kernel<<<B, 64>>>(x, pa, nullptr, out, ld, 1, B);
}

// round 5
// speedup vs baseline: 2.6070x; 2.6070x over previous
#include <cuda_runtime.h>
#include <cuda_bf16.h>
#include <math.h>
#include <stdint.h>

// ---------------------------------------------------------------------------
// NSF coupling layer on GB300 (compute_103-safe tensor path).
//   FCNN: 64 -> 512 -> 512 -> 1472 (x2), RQS spline (x2).
//   GEMMs via mma.sync.m16n8k16 bf16 (HMMA), 3-term split precision:
//     D = Ah*Bh + Ah*Bl + Al*Bh   (fp32 accumulate in registers)
//   cp.async 2-stage pipeline, ldmatrix with XOR-swizzled SMEM.
// ---------------------------------------------------------------------------

#define MAXB 32768
#define HD   512
#define PDIM 1472
#define PPAD 1536

// ------------------------- scratch (device globals) ------------------------
__device__ __align__(128) __nv_bfloat16 g_xl_hi[(size_t)MAXB * 64];
__device__ __align__(128) __nv_bfloat16 g_xl_lo[(size_t)MAXB * 64];
__device__ __align__(128) __nv_bfloat16 g_up_hi[(size_t)MAXB * 64];
__device__ __align__(128) __nv_bfloat16 g_up_lo[(size_t)MAXB * 64];
__device__ __align__(128) __nv_bfloat16 g_hA_hi[(size_t)MAXB * HD];
__device__ __align__(128) __nv_bfloat16 g_hA_lo[(size_t)MAXB * HD];
__device__ __align__(128) __nv_bfloat16 g_hB_hi[(size_t)MAXB * HD];
__device__ __align__(128) __nv_bfloat16 g_hB_lo[(size_t)MAXB * HD];
__device__ __align__(128) float g_params[(size_t)MAXB * PDIM];
__device__ __align__(128) float g_ld[MAXB];
__device__ __align__(128) __nv_bfloat16 g_w1t_hi[512 * 64];
__device__ __align__(128) __nv_bfloat16 g_w1t_lo[512 * 64];
__device__ __align__(128) __nv_bfloat16 g_w2t_hi[512 * 512];
__device__ __align__(128) __nv_bfloat16 g_w2t_lo[512 * 512];
__device__ __align__(128) __nv_bfloat16 g_w3t_hi[PPAD * 512];
__device__ __align__(128) __nv_bfloat16 g_w3t_lo[PPAD * 512];

// ------------------------- low-level helpers -------------------------------
__device__ __forceinline__ uint32_t smem_u32(const void* p) {
    uint32_t a;
    asm("{ .reg .u64 t; cvta.to.shared.u64 t, %1; cvt.u32.u64 %0, t; }"
        : "=r"(a) : "l"(p));
    return a;
}

__device__ __forceinline__ void ldsm4(uint32_t* r, uint32_t addr) {
    asm volatile("ldmatrix.sync.aligned.m8n8.x4.shared.b16 {%0,%1,%2,%3}, [%4];"
                 : "=r"(r[0]), "=r"(r[1]), "=r"(r[2]), "=r"(r[3]) : "r"(addr));
}

__device__ __forceinline__ void mma16816(float* c, const uint32_t* a,
                                         const uint32_t* b) {
    asm volatile(
        "mma.sync.aligned.m16n8k16.row.col.f32.bf16.bf16.f32 "
        "{%0,%1,%2,%3}, {%4,%5,%6,%7}, {%8,%9}, {%0,%1,%2,%3};"
        : "+f"(c[0]), "+f"(c[1]), "+f"(c[2]), "+f"(c[3])
        : "r"(a[0]), "r"(a[1]), "r"(a[2]), "r"(a[3]), "r"(b[0]), "r"(b[1]));
}

#define CP_ASYNC16(sa, gp) \
    asm volatile("cp.async.cg.shared.global [%0], [%1], 16;" :: "r"(sa), "l"(gp))
#define CP_COMMIT() asm volatile("cp.async.commit_group;" ::: "memory")
#define CP_WAIT0()  asm volatile("cp.async.wait_group 0;" ::: "memory")

// ---------------------------------------------------------------------------
// HMMA GEMM:  C[M, Nreal] = A[M,K] @ Wt[Npad,K]^T + bias  (opt SiLU)
// CTA 128x128, BK=32, 8 warps (2 M x 4 N), warp tile 64x32.
// SMEM per matrix tile: 128 rows x 32 bf16 (64 B/row), XOR-swizzled 16B chunks:
//   phys = row*64 + ((chunk ^ ((row>>1)&3)) << 4)
// Stage = {Ah, Al, Bh, Bl} = 4 * 8KB = 32KB; two stages = 64KB.
// ---------------------------------------------------------------------------
__device__ __forceinline__ void load_stage(
    uint32_t sbase,
    const __nv_bfloat16* ah, const __nv_bfloat16* al,
    const __nv_bfloat16* bh, const __nv_bfloat16* bl,
    int lda, int ldb, int tid)
{
#pragma unroll
    for (int it = 0; it < 8; it++) {
        const int idx = it * 256 + tid;
        const int mat = idx >> 9;        // constant per unroll pair
        const int cid = idx & 511;
        const int row = cid >> 2;
        const int ch  = cid & 3;
        const int ld  = (mat < 2) ? lda : ldb;
        const __nv_bfloat16* g =
            (mat == 0) ? ah : (mat == 1) ? al : (mat == 2) ? bh : bl;
        const void* gp = g + (size_t)row * ld + ch * 8;
        const uint32_t sa =
            sbase + mat * 8192 + row * 64 + ((ch ^ ((row >> 1) & 3)) << 4);
        CP_ASYNC16(sa, gp);
    }
}

template <int ACT, int SPLIT>
__global__ __launch_bounds__(256)
void gemm_hmma(const __nv_bfloat16* __restrict__ Ah,
               const __nv_bfloat16* __restrict__ Al, int lda,
               const __nv_bfloat16* __restrict__ Bh,
               const __nv_bfloat16* __restrict__ Bl,
               const float* __restrict__ bias,
               float* __restrict__ outf,
               __nv_bfloat16* __restrict__ oh,
               __nv_bfloat16* __restrict__ ol,
               int Nreal, int K)
{
    extern __shared__ char smem[];
    const uint32_t sbase = smem_u32(smem);

    const int tid  = threadIdx.x;
    const int lane = tid & 31;
    const int wid  = tid >> 5;
    const int warp_m = (wid >> 2) * 64;   // 0 or 64
    const int warp_n = (wid & 3) * 32;    // 0,32,64,96
    const int m0 = blockIdx.y * 128;
    const int n0 = blockIdx.x * 128;

    const __nv_bfloat16* Ahp = Ah + (size_t)m0 * lda;
    const __nv_bfloat16* Alp = Al + (size_t)m0 * lda;
    const __nv_bfloat16* Bhp = Bh + (size_t)n0 * K;
    const __nv_bfloat16* Blp = Bl + (size_t)n0 * K;

    float acc[4][4][4];
#pragma unroll
    for (int i = 0; i < 4; i++)
#pragma unroll
        for (int j = 0; j < 4; j++)
#pragma unroll
            for (int q = 0; q < 4; q++) acc[i][j][q] = 0.f;

    const int nk = K >> 5;  // BK = 32

    load_stage(sbase, Ahp, Alp, Bhp, Blp, lda, K, tid);
    CP_COMMIT();

    for (int kc = 0; kc < nk; kc++) {
        CP_WAIT0();
        __syncthreads();

        if (kc + 1 < nk) {
            const int ko = (kc + 1) * 32;
            load_stage(sbase + ((kc + 1) & 1) * 32768,
                       Ahp + ko, Alp + ko, Bhp + ko, Blp + ko, lda, K, tid);
            CP_COMMIT();
        }

        const uint32_t st = sbase + (kc & 1) * 32768;
        const uint32_t aH = st, aL = st + 8192, bH = st + 16384, bL = st + 24576;

#pragma unroll
        for (int s = 0; s < 2; s++) {  // two k16 steps per chunk
            uint32_t ah[4][4], al[4][4];
            const int chA = s * 2 + (lane >> 4);
#pragma unroll
            for (int i = 0; i < 4; i++) {
                const int r = warp_m + i * 16 + (lane & 15);
                const uint32_t off =
                    r * 64 + ((chA ^ ((r >> 1) & 3)) << 4);
                ldsm4(ah[i], aH + off);
                ldsm4(al[i], aL + off);
            }
            uint32_t bh[2][4], bl[2][4];
            const int chB = s * 2 + ((lane >> 3) & 1);
#pragma unroll
            for (int j2 = 0; j2 < 2; j2++) {
                const int n = warp_n + j2 * 16 + (lane & 7) + ((lane >> 4) << 3);
                const uint32_t off =
                    n * 64 + ((chB ^ ((n >> 1) & 3)) << 4);
                ldsm4(bh[j2], bH + off);
                ldsm4(bl[j2], bL + off);
            }
#pragma unroll
            for (int i = 0; i < 4; i++)
#pragma unroll
                for (int j = 0; j < 4; j++) {
                    float* c = acc[i][j];
                    const uint32_t* pbh = &bh[j >> 1][(j & 1) * 2];
                    const uint32_t* pbl = &bl[j >> 1][(j & 1) * 2];
                    mma16816(c, ah[i], pbh);   // Ah*Bh
                    mma16816(c, ah[i], pbl);   // Ah*Bl
                    mma16816(c, al[i], pbh);   // Al*Bh
                }
        }
        __syncthreads();
    }

    // ---- epilogue: bias + opt SiLU + store (fp32 or bf16 hi/lo split) ----
#pragma unroll
    for (int i = 0; i < 4; i++) {
        const int r0 = m0 + warp_m + i * 16 + (lane >> 2);
#pragma unroll
        for (int j = 0; j < 4; j++) {
            const int col = n0 + warp_n + j * 8 + ((lane & 3) << 1);
            if (col < Nreal) {
                const float b0 = bias[col];
                const float b1 = bias[col + 1];
#pragma unroll
                for (int h = 0; h < 2; h++) {
                    const int r = r0 + h * 8;
                    float v0 = acc[i][j][h * 2 + 0] + b0;
                    float v1 = acc[i][j][h * 2 + 1] + b1;
                    if (ACT) {
                        v0 = v0 / (1.f + __expf(-v0));
                        v1 = v1 / (1.f + __expf(-v1));
                    }
                    const size_t ob = (size_t)r * Nreal + col;
                    if (SPLIT) {
                        const __nv_bfloat16 h0 = __float2bfloat16(v0);
                        const __nv_bfloat16 h1 = __float2bfloat16(v1);
                        *reinterpret_cast<__nv_bfloat162*>(oh + ob) =
                            __halves2bfloat162(h0, h1);
                        *reinterpret_cast<__nv_bfloat162*>(ol + ob) =
                            __halves2bfloat162(
                                __float2bfloat16(v0 - __bfloat162float(h0)),
                                __float2bfloat16(v1 - __bfloat162float(h1)));
                    } else {
                        float2 v; v.x = v0; v.y = v1;
                        *reinterpret_cast<float2*>(outf + ob) = v;
                    }
                }
            }
        }
    }
}

// ---------------------------------------------------------------------------
// Conversion kernels (bf16 hi/lo split)
// ---------------------------------------------------------------------------
__global__ void prep_x_kernel(const float* __restrict__ x,
                              __nv_bfloat16* __restrict__ hi,
                              __nv_bfloat16* __restrict__ lo, int total)
{
    int idx = blockIdx.x * blockDim.x + threadIdx.x;
    if (idx >= total) return;
    int b = idx >> 6, j = idx & 63;
    float v = x[(size_t)b * 128 + j];
    __nv_bfloat16 h = __float2bfloat16(v);
    hi[idx] = h;
    lo[idx] = __float2bfloat16(v - __bfloat162float(h));
}

// W [K,N] fp32 row-major -> Wt [Npad, K] bf16 hi/lo (transposed, zero-padded)
__global__ void conv_w_kernel(const float* __restrict__ W, int K, int N, int Npad,
                              __nv_bfloat16* __restrict__ hi,
                              __nv_bfloat16* __restrict__ lo)
{
    int idx = blockIdx.x * blockDim.x + threadIdx.x;
    if (idx >= Npad * K) return;
    int n = idx / K, k = idx - n * K;
    float v = (n < N) ? W[(size_t)k * N + n] : 0.f;
    __nv_bfloat16 h = __float2bfloat16(v);
    hi[idx] = h;
    lo[idx] = __float2bfloat16(v - __bfloat162float(h));
}

// ---------------------------------------------------------------------------
// RQS spline + logdet.
// ---------------------------------------------------------------------------
__device__ __forceinline__ float softplusf(float v)
{
    return (v > 20.f) ? v : log1pf(expf(v));
}

__global__ __launch_bounds__(64)
void rqs_kernel(const float* __restrict__ x,
                const float* __restrict__ params,
                __nv_bfloat16* __restrict__ up_hi,
                __nv_bfloat16* __restrict__ up_lo,
                float* __restrict__ dout,
                float* __restrict__ ld_buf,
                int phase, int Bn)
{
    const int b = blockIdx.x;
    const int j = threadIdx.x;  // 0..63

    const float xv = x[(size_t)b * 128 + (phase == 0 ? 64 + j : j)];
    const float* p = params + (size_t)b * PDIM + j * 23;

    float W[8], H[8], D7[7];
#pragma unroll
    for (int i = 0; i < 8; i++) W[i] = p[i];
#pragma unroll
    for (int i = 0; i < 8; i++) H[i] = p[8 + i];
#pragma unroll
    for (int i = 0; i < 7; i++) D7[i] = p[16 + i];

    float mw = W[0];
#pragma unroll
    for (int i = 1; i < 8; i++) mw = fmaxf(mw, W[i]);
    float sw = 0.f;
#pragma unroll
    for (int i = 0; i < 8; i++) { W[i] = expf(W[i] - mw); sw += W[i]; }
    const float invw = 1.f / sw;

    float mh = H[0];
#pragma unroll
    for (int i = 1; i < 8; i++) mh = fmaxf(mh, H[i]);
    float sh = 0.f;
#pragma unroll
    for (int i = 0; i < 8; i++) { H[i] = expf(H[i] - mh); sh += H[i]; }
    const float invh = 1.f / sh;

    float cumw[9], cumh[9];
    cumw[0] = 0.f; cumh[0] = 0.f;
#pragma unroll
    for (int i = 0; i < 8; i++) {
        cumw[i + 1] = cumw[i] + (0.001f + 0.992f * W[i] * invw);
        cumh[i + 1] = cumh[i] + (0.001f + 0.992f * H[i] * invh);
    }
#pragma unroll
    for (int i = 0; i < 9; i++) {
        cumw[i] = 2.f * cumw[i] - 1.f;
        cumh[i] = 2.f * cumh[i] - 1.f;
    }
    cumw[0] = -1.f; cumw[8] = 1.f;
    cumh[0] = -1.f; cumh[8] = 1.f;

    float d[9];
    const float CST = logf(expf(1.0f - 0.001f) - 1.0f);
    const float dpad = 0.001f + softplusf(CST);
    d[0] = dpad; d[8] = dpad;
#pragma unroll
    for (int i = 0; i < 7; i++) d[i + 1] = 0.001f + softplusf(D7[i]);

    int idx = 0;
#pragma unroll
    for (int i = 0; i < 9; i++) {
        float loc = cumw[i] + ((i == 8) ? 1e-6f : 0.f);
        idx += (xv >= loc) ? 1 : 0;
    }
    idx -= 1;
    idx = max(0, min(7, idx));

    float icw = 0.f, iw = 1.f, ich = 0.f, ih = 1.f, d0 = 1.f, d1 = 1.f;
#pragma unroll
    for (int i = 0; i < 8; i++) {
        if (i == idx) {
            icw = cumw[i]; iw = cumw[i + 1] - cumw[i];
            ich = cumh[i]; ih = cumh[i + 1] - cumh[i];
            d0 = d[i]; d1 = d[i + 1];
        }
    }
    const float idel = ih / iw;
    const float th   = (xv - icw) / iw;
    const float omt  = 1.f - th;
    const float t1mt = th * omt;

    const float numer = ih * (idel * th * th + d0 * t1mt);
    const float den   = idel + (d0 + d1 - 2.f * idel) * t1mt;
    float out = ich + numer / den;

    const float dnum = idel * idel *
        (d1 * th * th + 2.f * idel * t1mt + d0 * omt * omt);
    float lad = logf(dnum) - 2.f * logf(den);

    const bool inside = (xv >= -1.f) && (xv <= 1.f);
    if (!inside) { out = xv; lad = 0.f; }

    if (phase == 0) {
        dout[(size_t)b * 128 + 64 + j] = out;
        __nv_bfloat16 h = __float2bfloat16(out);
        up_hi[(size_t)b * 64 + j] = h;
        up_lo[(size_t)b * 64 + j] = __float2bfloat16(out - __bfloat162float(h));
    } else {
        dout[(size_t)b * 128 + j] = out;
    }

    float v = lad;
#pragma unroll
    for (int off = 16; off > 0; off >>= 1)
        v += __shfl_down_sync(0xffffffffu, v, off);
    __shared__ float sred[2];
    if ((j & 31) == 0) sred[j >> 5] = v;
    __syncthreads();
    if (j == 0) {
        const float tot = sred[0] + sred[1];
        if (phase == 0) ld_buf[b] = tot;
        else dout[(size_t)Bn * 128 + b] = ld_buf[b] + tot;
    }
}

// ---------------------------------------------------------------------------
// Launch
// ---------------------------------------------------------------------------
extern "C" void kernel_launch(void* const* d_in, const int* in_sizes, int n_in,
                              void* d_out, int out_size)
{
    const float* x    = (const float*)d_in[0];
    const float* f1w1 = (const float*)d_in[1];
    const float* f1b1 = (const float*)d_in[2];
    const float* f1w2 = (const float*)d_in[3];
    const float* f1b2 = (const float*)d_in[4];
    const float* f1w3 = (const float*)d_in[5];
    const float* f1b3 = (const float*)d_in[6];
    const float* f2w1 = (const float*)d_in[7];
    const float* f2b1 = (const float*)d_in[8];
    const float* f2w2 = (const float*)d_in[9];
    const float* f2b2 = (const float*)d_in[10];
    const float* f2w3 = (const float*)d_in[11];
    const float* f2b3 = (const float*)d_in[12];
    float* out = (float*)d_out;

    const int B = in_sizes[0] / 128;

    __nv_bfloat16 *xlh, *xll, *uph, *upl, *hAh, *hAl, *hBh, *hBl;
    __nv_bfloat16 *w1h, *w1l, *w2h, *w2l, *w3h, *w3l;
    float *pa, *ld;
    cudaGetSymbolAddress((void**)&xlh, g_xl_hi);
    cudaGetSymbolAddress((void**)&xll, g_xl_lo);
    cudaGetSymbolAddress((void**)&uph, g_up_hi);
    cudaGetSymbolAddress((void**)&upl, g_up_lo);
    cudaGetSymbolAddress((void**)&hAh, g_hA_hi);
    cudaGetSymbolAddress((void**)&hAl, g_hA_lo);
    cudaGetSymbolAddress((void**)&hBh, g_hB_hi);
    cudaGetSymbolAddress((void**)&hBl, g_hB_lo);
    cudaGetSymbolAddress((void**)&w1h, g_w1t_hi);
    cudaGetSymbolAddress((void**)&w1l, g_w1t_lo);
    cudaGetSymbolAddress((void**)&w2h, g_w2t_hi);
    cudaGetSymbolAddress((void**)&w2l, g_w2t_lo);
    cudaGetSymbolAddress((void**)&w3h, g_w3t_hi);
    cudaGetSymbolAddress((void**)&w3l, g_w3t_lo);
    cudaGetSymbolAddress((void**)&pa, g_params);
    cudaGetSymbolAddress((void**)&ld, g_ld);

    const int DSMEM = 65536;  // 2 stages x 32 KB
    cudaFuncSetAttribute((const void*)gemm_hmma<1, 1>,
                         cudaFuncAttributeMaxDynamicSharedMemorySize, DSMEM);
    cudaFuncSetAttribute((const void*)gemm_hmma<0, 0>,
                         cudaFuncAttributeMaxDynamicSharedMemorySize, DSMEM);

    const int MB = B / 128;

    prep_x_kernel<<<(B * 64 + 255) / 256, 256>>>(x, xlh, xll, B * 64);

    // ---- FCNN1 ----
    conv_w_kernel<<<(512 * 64 + 255) / 256, 256>>>(f1w1, 64, 512, 512, w1h, w1l);
    conv_w_kernel<<<(512 * 512 + 255) / 256, 256>>>(f1w2, 512, 512, 512, w2h, w2l);
    conv_w_kernel<<<(PPAD * 512 + 255) / 256, 256>>>(f1w3, 512, PDIM, PPAD, w3h, w3l);

    gemm_hmma<1, 1><<<dim3(4, MB), 256, DSMEM>>>(xlh, xll, 64, w1h, w1l, f1b1,
                                                 nullptr, hAh, hAl, 512, 64);
    gemm_hmma<1, 1><<<dim3(4, MB), 256, DSMEM>>>(hAh, hAl, 512, w2h, w2l, f1b2,
                                                 nullptr, hBh, hBl, 512, 512);
    gemm_hmma<0, 0><<<dim3(PPAD / 128, MB), 256, DSMEM>>>(hBh, hBl, 512, w3h, w3l,
                                                          f1b3, pa, nullptr, nullptr,
                                                          PDIM, 512);

    rqs_kernel<<<B, 64>>>(x, pa, uph, upl, out, ld, 0, B);

    // ---- FCNN2 (reuse weight buffers) ----
    conv_w_kernel<<<(512 * 64 + 255) / 256, 256>>>(f2w1, 64, 512, 512, w1h, w1l);
    conv_w_kernel<<<(512 * 512 + 255) / 256, 256>>>(f2w2, 512, 512, 512, w2h, w2l);
    conv_w_kernel<<<(PPAD * 512 + 255) / 256, 256>>>(f2w3, 512, PDIM, PPAD, w3h, w3l);

    gemm_hmma<1, 1><<<dim3(4, MB), 256, DSMEM>>>(uph, upl, 64, w1h, w1l, f2b1,
                                                 nullptr, hAh, hAl, 512, 64);
    gemm_hmma<1, 1><<<dim3(4, MB), 256, DSMEM>>>(hAh, hAl, 512, w2h, w2l, f2b2,
                                                 nullptr, hBh, hBl, 512, 512);
    gemm_hmma<0, 0><<<dim3(PPAD / 128, MB), 256, DSMEM>>>(hBh, hBl, 512, w3h, w3l,
                                                          f2b3, pa, nullptr, nullptr,
                                                          PDIM, 512);

    rqs_kernel<<<B, 64>>>(x, pa, nullptr, nullptr, out, ld, 1, B);
}